// round 3
// baseline (speedup 1.0000x reference)
#include <cuda_runtime.h>

#define Nn 100000
#define Dd 128
#define Cc 40
#define Ee 1600000
#define SCAN_B 1024
#define NB_SCAN ((Nn + SCAN_B - 1) / SCAN_B)   // 98

// ---------------- scratch (static __device__ allowed; no cudaMalloc) ----------
__device__ float g_A[(size_t)Nn * Dd];   // 51.2 MB ping
__device__ float g_B[(size_t)Nn * Dd];   // 51.2 MB pong
__device__ int   g_deg[Nn];
__device__ float g_dinv[Nn];
__device__ float g_dinvl[Nn];
__device__ int   g_rowptr[Nn + 1];
__device__ int   g_cursor[Nn];
__device__ int   g_csrc[Ee];
__device__ int   g_bsums[128];
__device__ float g_colsum[Dd];
__device__ float g_ss;
__device__ float g_mu[Dd];
__device__ float g_scale;
__device__ int   g_is64;

// --------------- edge dtype detection (jax x64 quirk) -------------------------
__global__ void k_detect(const long long* __restrict__ ei) {
    if (blockIdx.x == 0 && threadIdx.x == 0) {
        int ok = 1;
        for (int i = 0; i < 1024; i++) {
            long long v = ei[i];
            if (v < 0 || v >= (long long)Nn) { ok = 0; break; }
        }
        g_is64 = ok;
    }
}

// --------------- init / degree / dinv ----------------------------------------
__global__ void k_zero_nodes() {
    int i = blockIdx.x * blockDim.x + threadIdx.x;
    if (i < Nn) { g_deg[i] = 0; g_cursor[i] = 0; }
}

__global__ void k_degree(const long long* __restrict__ ei) {
    int e = blockIdx.x * blockDim.x + threadIdx.x;
    if (e >= Ee) return;
    int d;
    if (g_is64) d = (int)ei[(size_t)Ee + e];
    else        d = ((const int*)ei)[(size_t)Ee + e];
    atomicAdd(&g_deg[d], 1);
}

__global__ void k_dinv() {
    int i = blockIdx.x * blockDim.x + threadIdx.x;
    if (i >= Nn) return;
    int d = g_deg[i];
    g_dinv[i]  = (d > 0) ? rsqrtf((float)d) : 0.0f;
    g_dinvl[i] = rsqrtf((float)(d + 1));
}

// --------------- exclusive scan of deg -> rowptr ------------------------------
__global__ void k_scan1() {
    __shared__ int sh[SCAN_B];
    int t = threadIdx.x;
    int i = blockIdx.x * SCAN_B + t;
    int v = (i < Nn) ? g_deg[i] : 0;
    sh[t] = v;
    __syncthreads();
    for (int off = 1; off < SCAN_B; off <<= 1) {
        int x = (t >= off) ? sh[t - off] : 0;
        __syncthreads();
        sh[t] += x;
        __syncthreads();
    }
    if (i < Nn) g_rowptr[i] = sh[t] - v;            // exclusive
    if (t == SCAN_B - 1) g_bsums[blockIdx.x] = sh[t];
}

__global__ void k_scan2() {
    if (blockIdx.x == 0 && threadIdx.x == 0) {
        int acc = 0;
        for (int b = 0; b < NB_SCAN; b++) { int x = g_bsums[b]; g_bsums[b] = acc; acc += x; }
    }
}

__global__ void k_scan3() {
    int i = blockIdx.x * blockDim.x + threadIdx.x;
    if (i < Nn) g_rowptr[i] += g_bsums[i / SCAN_B];
    if (i == 0) g_rowptr[Nn] = Ee;
}

__global__ void k_fill(const long long* __restrict__ ei) {
    int e = blockIdx.x * blockDim.x + threadIdx.x;
    if (e >= Ee) return;
    int s, d;
    if (g_is64) { s = (int)ei[e]; d = (int)ei[(size_t)Ee + e]; }
    else        { const int* e32 = (const int*)ei; s = e32[e]; d = e32[(size_t)Ee + e]; }
    int pos = g_rowptr[d] + atomicAdd(&g_cursor[d], 1);
    g_csrc[pos] = s;
}

// --------------- GEMM 128x128: H = f(X) @ W ----------------------------------
// tile 64 rows x 128 cols, 256 threads, 8x4 per thread. dynamic smem 96KB.
__global__ __launch_bounds__(256, 2) void k_gemm128(
    const float* __restrict__ X, const float* __restrict__ W,
    float* __restrict__ H, int useT)
{
    extern __shared__ float smem[];
    float*  Ws  = smem;                 // 128*128
    float*  Xs  = smem + 128 * 128;     // 64*128
    float4* Wsv = (float4*)Ws;
    float4* Xsv = (float4*)Xs;
    int t = threadIdx.x;
    int r0 = blockIdx.x * 64;

    // load W (16384 floats = 4096 float4)
    const float4* Wg = (const float4*)W;
    #pragma unroll
    for (int i = 0; i < 16; i++) Wsv[t + i * 256] = Wg[t + i * 256];

    // load X tile with optional (v-mu)*s, relu transform
    float sc = useT ? g_scale : 1.0f;
    #pragma unroll
    for (int i = 0; i < 8; i++) {
        int idx = t + i * 256;              // 0..2047
        int row = idx >> 5, v = idx & 31;
        int gr = r0 + row;
        float4 vv = make_float4(0.f, 0.f, 0.f, 0.f);
        if (gr < Nn) vv = ((const float4*)(X + (size_t)gr * 128))[v];
        if (useT) {
            float4 m = ((const float4*)g_mu)[v];
            vv.x = fmaxf((vv.x - m.x) * sc, 0.f);
            vv.y = fmaxf((vv.y - m.y) * sc, 0.f);
            vv.z = fmaxf((vv.z - m.z) * sc, 0.f);
            vv.w = fmaxf((vv.w - m.w) * sc, 0.f);
        }
        Xsv[row * 32 + v] = vv;
    }
    __syncthreads();

    int tx = t & 31, ty = t >> 5;
    float acc[8][4];
    #pragma unroll
    for (int i = 0; i < 8; i++) { acc[i][0]=0;acc[i][1]=0;acc[i][2]=0;acc[i][3]=0; }

    #pragma unroll 2
    for (int k = 0; k < 128; k++) {
        float4 b = Wsv[k * 32 + tx];
        float a[8];
        #pragma unroll
        for (int i = 0; i < 8; i++) a[i] = Xs[(ty * 8 + i) * 128 + k];
        #pragma unroll
        for (int i = 0; i < 8; i++) {
            acc[i][0] += a[i] * b.x;
            acc[i][1] += a[i] * b.y;
            acc[i][2] += a[i] * b.z;
            acc[i][3] += a[i] * b.w;
        }
    }

    #pragma unroll
    for (int i = 0; i < 8; i++) {
        int r = r0 + ty * 8 + i;
        if (r < Nn) {
            float4 o = make_float4(acc[i][0], acc[i][1], acc[i][2], acc[i][3]);
            *(float4*)(H + (size_t)r * 128 + tx * 4) = o;
        }
    }
}

// --------------- GEMM 128x40 (last layer, transform always) -------------------
__global__ __launch_bounds__(256) void k_gemm40(
    const float* __restrict__ X, const float* __restrict__ W, float* __restrict__ H)
{
    __shared__ float Ws[128 * 40];
    int t = threadIdx.x;
    #pragma unroll
    for (int i = 0; i < 20; i++) Ws[t + i * 256] = W[t + i * 256];
    __syncthreads();

    int row = blockIdx.x * 256 + t;
    if (row >= Nn) return;
    float sc = g_scale;
    float2 acc[20];
    #pragma unroll
    for (int c = 0; c < 20; c++) acc[c] = make_float2(0.f, 0.f);

    const float4* xr = (const float4*)(X + (size_t)row * 128);
    for (int k4 = 0; k4 < 32; k4++) {
        float4 xv = xr[k4];
        float4 m4 = ((const float4*)g_mu)[k4];
        float xa[4] = { fmaxf((xv.x - m4.x) * sc, 0.f), fmaxf((xv.y - m4.y) * sc, 0.f),
                        fmaxf((xv.z - m4.z) * sc, 0.f), fmaxf((xv.w - m4.w) * sc, 0.f) };
        #pragma unroll
        for (int j = 0; j < 4; j++) {
            float a = xa[j];
            const float2* wr = (const float2*)(Ws + (k4 * 4 + j) * 40);
            #pragma unroll
            for (int c = 0; c < 20; c++) {
                float2 w = wr[c];
                acc[c].x += a * w.x;
                acc[c].y += a * w.y;
            }
        }
    }
    float2* o = (float2*)(H + (size_t)row * 40);
    #pragma unroll
    for (int c = 0; c < 20; c++) o[c] = acc[c];
}

// --------------- aggregation 128 cols (warp per node) + fused stats ----------
__global__ __launch_bounds__(256) void k_agg128(
    const float* __restrict__ H, float* __restrict__ O,
    const float* __restrict__ bias, int stats)
{
    __shared__ float s_cs[128];
    __shared__ float s_ss;
    int t = threadIdx.x, lane = t & 31, w = t >> 5;
    if (t < 128) s_cs[t] = 0.f;
    if (t == 0)  s_ss = 0.f;

    int node = blockIdx.x * 8 + w;
    float4 ov = make_float4(0.f, 0.f, 0.f, 0.f);
    bool active = (node < Nn);
    if (active) {
        int start = g_rowptr[node], end = g_rowptr[node + 1];
        float4 acc = make_float4(0.f, 0.f, 0.f, 0.f);
        #pragma unroll 4
        for (int e = start; e < end; e++) {
            int s   = g_csrc[e];          // uniform across warp (broadcast)
            float ww = g_dinv[s];
            float4 v = *(const float4*)(H + (size_t)s * 128 + lane * 4);
            acc.x += ww * v.x; acc.y += ww * v.y;
            acc.z += ww * v.z; acc.w += ww * v.w;
        }
        float di = g_dinv[node];
        float4 b4 = ((const float4*)bias)[lane];
        ov.x = acc.x * di + b4.x;
        ov.y = acc.y * di + b4.y;
        ov.z = acc.z * di + b4.z;
        ov.w = acc.w * di + b4.w;
        *(float4*)(O + (size_t)node * 128 + lane * 4) = ov;
    }
    __syncthreads();
    if (stats) {
        if (active) {
            atomicAdd(&s_cs[lane * 4 + 0], ov.x);
            atomicAdd(&s_cs[lane * 4 + 1], ov.y);
            atomicAdd(&s_cs[lane * 4 + 2], ov.z);
            atomicAdd(&s_cs[lane * 4 + 3], ov.w);
            float ssv = ov.x * ov.x + ov.y * ov.y + ov.z * ov.z + ov.w * ov.w;
            #pragma unroll
            for (int off = 16; off >= 1; off >>= 1)
                ssv += __shfl_xor_sync(0xffffffffu, ssv, off);
            if (lane == 0) atomicAdd(&s_ss, ssv);
        }
        __syncthreads();
        if (t < 128) atomicAdd(&g_colsum[t], s_cs[t]);
        if (t == 0)  atomicAdd(&g_ss, s_ss);
    }
}

// --------------- pairnorm params ----------------------------------------------
__global__ void k_zero_stats() {
    int t = threadIdx.x;
    if (t < 128) g_colsum[t] = 0.f;
    if (t == 0)  g_ss = 0.f;
}

__global__ void k_pnorm() {
    __shared__ float sh[128];
    int t = threadIdx.x;
    float mu = g_colsum[t] * (1.0f / (float)Nn);
    g_mu[t] = mu;
    sh[t] = mu * mu;
    __syncthreads();
    for (int off = 64; off >= 1; off >>= 1) {
        if (t < off) sh[t] += sh[t + off];
        __syncthreads();
    }
    if (t == 0) {
        float var = (g_ss - (float)Nn * sh[0]) * (1.0f / (float)Nn);
        g_scale = rsqrtf(1e-6f + var);
    }
}

// --------------- final aggregation (40 cols, self loops) ----------------------
__global__ __launch_bounds__(256) void k_agg40(
    const float* __restrict__ H, float* __restrict__ O, const float* __restrict__ b3)
{
    int t = threadIdx.x, lane = t & 31, w = t >> 5;
    int node = blockIdx.x * 8 + w;
    if (node >= Nn) return;
    int start = g_rowptr[node], end = g_rowptr[node + 1];
    float2 acc = make_float2(0.f, 0.f);
    #pragma unroll 4
    for (int e = start; e < end; e++) {
        int s   = g_csrc[e];
        float ww = g_dinvl[s];
        if (lane < 20) {
            float2 v = *(const float2*)(H + (size_t)s * 40 + lane * 2);
            acc.x += ww * v.x;
            acc.y += ww * v.y;
        }
    }
    float dl = g_dinvl[node];
    if (lane < 20) {
        float2 hv = *(const float2*)(H + (size_t)node * 40 + lane * 2);
        acc.x += dl * hv.x;       // self loop: norm = dl*dl, one dl here, one below
        acc.y += dl * hv.y;
        float2 bb = ((const float2*)b3)[lane];
        float2 o;
        o.x = acc.x * dl + bb.x;
        o.y = acc.y * dl + bb.y;
        *(float2*)(O + (size_t)node * 40 + lane * 2) = o;
    }
}

// ------------------------------------------------------------------------------
extern "C" void kernel_launch(void* const* d_in, const int* in_sizes, int n_in,
                              void* d_out, int out_size)
{
    const float*     x  = (const float*)d_in[0];
    const long long* ei = (const long long*)d_in[1];
    const float* W0 = (const float*)d_in[2];
    const float* W1 = (const float*)d_in[3];
    const float* W2 = (const float*)d_in[4];
    const float* W3 = (const float*)d_in[5];
    const float* b0 = (const float*)d_in[6];
    const float* b1 = (const float*)d_in[7];
    const float* b2 = (const float*)d_in[8];
    const float* b3 = (const float*)d_in[9];
    float* out = (float*)d_out;

    cudaFuncSetAttribute(k_gemm128, cudaFuncAttributeMaxDynamicSharedMemorySize, 98304);

    const int TB = 256;
    int gN = (Nn + TB - 1) / TB;        // 391
    int gE = (Ee + TB - 1) / TB;        // 6250
    int gG = (Nn + 63) / 64;            // 1563 (gemm128 row tiles)
    int gA = (Nn + 7) / 8;              // 12500 (warp-per-node aggs)

    // graph / CSR build
    k_detect<<<1, 32>>>(ei);
    k_zero_nodes<<<gN, TB>>>();
    k_degree<<<gE, TB>>>(ei);
    k_dinv<<<gN, TB>>>();
    k_scan1<<<NB_SCAN, SCAN_B>>>();
    k_scan2<<<1, 32>>>();
    k_scan3<<<gN, TB>>>();
    k_fill<<<gE, TB>>>(ei);

    // layer 0
    k_gemm128<<<gG, TB, 98304>>>(x, W0, g_A, 0);
    k_zero_stats<<<1, 128>>>();
    k_agg128<<<gA, TB>>>(g_A, g_B, b0, 1);
    k_pnorm<<<1, 128>>>();

    // layer 1
    k_gemm128<<<gG, TB, 98304>>>(g_B, W1, g_A, 1);
    k_zero_stats<<<1, 128>>>();
    k_agg128<<<gA, TB>>>(g_A, g_B, b1, 1);
    k_pnorm<<<1, 128>>>();

    // layer 2
    k_gemm128<<<gG, TB, 98304>>>(g_B, W2, g_A, 1);
    k_zero_stats<<<1, 128>>>();
    k_agg128<<<gA, TB>>>(g_A, g_B, b2, 1);
    k_pnorm<<<1, 128>>>();

    // layer 3 (self loops, 40 cols)
    k_gemm40<<<gN, TB>>>(g_B, W3, g_A);
    k_agg40<<<gA, TB>>>(g_A, out, b3);
}